// round 16
// baseline (speedup 1.0000x reference)
#include <cuda_runtime.h>
#include <cstdint>

// Problem constants (shapes fixed by the reference).
#define NNODES 100000
#define INDIM  512
#define HIDDIM 256
#define OUTDIM 64
#define NEDGES 3200000

// ---------------------------------------------------------------------------
// Scratch (device globals — no runtime allocation allowed)
// ---------------------------------------------------------------------------
__device__ __align__(16) float g_dinv[NNODES];
__device__ __align__(16) int   g_cnt [NNODES];
__device__ __align__(16) int   g_off [NNODES];
__device__ __align__(16) int   g_pos [NNODES];
__device__ __align__(16) int   g_part[1024];
__device__ __align__(16) int   g_ssrc [NEDGES];
__device__ __align__(16) float g_snorm[NEDGES];
__device__ __align__(16) float g_h  [NNODES * HIDDIM];
__device__ __align__(16) float g_a1 [NNODES * HIDDIM];
__device__ __align__(16) float g_h2 [NNODES * OUTDIM];
__device__ int g_is64;

// ---------------------------------------------------------------------------
// Edge dtype detection (int64 vs int32 edge_index)
// ---------------------------------------------------------------------------
__global__ void k_detect(const void* __restrict__ ei, int E, int n) {
    int m = E < 1024 ? E : 1024;
    int ok = 1;
    const long long* p = (const long long*)ei;
    for (int i = threadIdx.x; i < m; i += blockDim.x) {
        long long v = p[i];
        if (v < 0 || v >= (long long)n) ok = 0;
    }
    int all = __syncthreads_and(ok);
    if (threadIdx.x == 0) g_is64 = all;
}
__device__ __forceinline__ int edge_at(const void* ei, long long idx) {
    if (g_is64) return (int)((const long long*)ei)[idx];
    return ((const int*)ei)[idx];
}

// ---------------------------------------------------------------------------
// Degree count + CSR build (bucketed by dst)
// ---------------------------------------------------------------------------
__global__ void k_init(int n) {
    int i = blockIdx.x * blockDim.x + threadIdx.x;
    if (i < n) g_cnt[i] = 0;
}
__global__ void k_count(const void* __restrict__ ei, int E) {
    int e = blockIdx.x * blockDim.x + threadIdx.x;
    if (e < E) atomicAdd(&g_cnt[edge_at(ei, (long long)E + e)], 1);
}
__global__ void k_dinv(int n) {
    int i = blockIdx.x * blockDim.x + threadIdx.x;
    if (i < n) g_dinv[i] = rsqrtf(1.0f + (float)g_cnt[i]);
}
__global__ void k_scan1(int n) {
    __shared__ int s[1024];
    int i = blockIdx.x * 1024 + threadIdx.x;
    int v = (i < n) ? g_cnt[i] : 0;
    s[threadIdx.x] = v;
    __syncthreads();
#pragma unroll
    for (int d = 1; d < 1024; d <<= 1) {
        int t = (threadIdx.x >= d) ? s[threadIdx.x - d] : 0;
        __syncthreads();
        s[threadIdx.x] += t;
        __syncthreads();
    }
    if (i < n) g_off[i] = s[threadIdx.x] - v;
    if (threadIdx.x == 1023) g_part[blockIdx.x] = s[1023];
}
__global__ void k_scan2(int nb) {
    __shared__ int s[1024];
    int v = (threadIdx.x < nb) ? g_part[threadIdx.x] : 0;
    s[threadIdx.x] = v;
    __syncthreads();
#pragma unroll
    for (int d = 1; d < 1024; d <<= 1) {
        int t = (threadIdx.x >= d) ? s[threadIdx.x - d] : 0;
        __syncthreads();
        s[threadIdx.x] += t;
        __syncthreads();
    }
    if (threadIdx.x < nb) g_part[threadIdx.x] = s[threadIdx.x] - v;
}
__global__ void k_scan3(int n) {
    int i = blockIdx.x * blockDim.x + threadIdx.x;
    if (i < n) {
        int o = g_off[i] + g_part[i >> 10];
        g_off[i] = o;
        g_pos[i] = o;
    }
}
__global__ void k_place(const void* __restrict__ ei, int E) {
    int e = blockIdx.x * blockDim.x + threadIdx.x;
    if (e < E) {
        int s = edge_at(ei, e);
        int d = edge_at(ei, (long long)E + e);
        int p = atomicAdd(&g_pos[d], 1);
        g_ssrc[p]  = s;
        g_snorm[p] = g_dinv[s] * g_dinv[d];
    }
}

// ---------------------------------------------------------------------------
// GEMM1: h[M,256] = x[M,512] @ W1[512,256]
// 2-stage double-buffered f32x2 kernel; small thread-tile for occupancy:
// BM=64, BN=128, TM=4, TN=4+4 (two dense col groups), 256 threads,
// 3 CTAs/SM (24 warps, 6/SMSP) to hide LDS/LDG latency.
// ---------------------------------------------------------------------------
#define G1_K 512
#define G1_N 256
#define G1_KT (G1_K / 8)   // 64 K-tiles

__global__ __launch_bounds__(256, 3)
void gemm1_db(const float* __restrict__ A, const float* __restrict__ B,
              float* __restrict__ C, int M)
{
    __shared__ __align__(16) float As[2][8][64];    // 2 KB x2
    __shared__ __align__(16) float Bs[2][8][128];   // 4 KB x2

    const int tid = threadIdx.x;
    const int tx  = tid & 15;          // 16 col-groups; cols tx*4 and 64+tx*4
    const int ty  = tid >> 4;          // 16 row-groups * 4 = 64 M rows
    const int m0  = blockIdx.y * 64;
    const int n0  = blockIdx.x * 128;

    const int ar = tid >> 1, ac = (tid & 1) * 4;     // A: 64x8 as 128 float4 (tid<128)
    const int br = tid >> 5, bc = (tid & 31) * 4;    // B: 8x128 as 256 float4
    const float4 fz = make_float4(0.f, 0.f, 0.f, 0.f);

    // prologue: tile 0
    float4 av = fz;
    if (tid < 128 && m0 + ar < M)
        av = *reinterpret_cast<const float4*>(&A[(size_t)(m0 + ar) * G1_K + ac]);
    float4 bv = *reinterpret_cast<const float4*>(&B[(size_t)br * G1_N + n0 + bc]);
    if (tid < 128) {
        As[0][ac + 0][ar] = av.x; As[0][ac + 1][ar] = av.y;
        As[0][ac + 2][ar] = av.z; As[0][ac + 3][ar] = av.w;
    }
    *reinterpret_cast<float4*>(&Bs[0][br][bc]) = bv;
    __syncthreads();

    unsigned long long acc[4][4];      // j=0,1: cols tx*4+{0,2}; j=2,3: 64+tx*4+{0,2}
#pragma unroll
    for (int i = 0; i < 4; i++)
#pragma unroll
        for (int j = 0; j < 4; j++) acc[i][j] = 0ull;

    for (int t = 0; t < G1_KT; t++) {
        const int cur = t & 1;
        if (t + 1 < G1_KT) {            // prefetch next tile into registers
            const int kk = (t + 1) * 8;
            if (tid < 128)
                av = (m0 + ar < M)
                    ? *reinterpret_cast<const float4*>(&A[(size_t)(m0 + ar) * G1_K + kk + ac]) : fz;
            bv = *reinterpret_cast<const float4*>(&B[(size_t)(kk + br) * G1_N + n0 + bc]);
        }
#pragma unroll
        for (int k = 0; k < 8; k++) {
            float4 a4 = *reinterpret_cast<const float4*>(&As[cur][k][ty * 4]);
            float a[4] = {a4.x, a4.y, a4.z, a4.w};
            ulonglong2 bg0 = *reinterpret_cast<const ulonglong2*>(&Bs[cur][k][tx * 4]);
            ulonglong2 bg1 = *reinterpret_cast<const ulonglong2*>(&Bs[cur][k][64 + tx * 4]);
            unsigned long long b2[4] = {bg0.x, bg0.y, bg1.x, bg1.y};
#pragma unroll
            for (int i = 0; i < 4; i++) {
                unsigned long long a2;
                unsigned int au = __float_as_uint(a[i]);
                asm("mov.b64 %0, {%1, %1};" : "=l"(a2) : "r"(au));
#pragma unroll
                for (int j = 0; j < 4; j++)
                    asm("fma.rn.f32x2 %0, %1, %2, %3;"
                        : "=l"(acc[i][j]) : "l"(a2), "l"(b2[j]), "l"(acc[i][j]));
            }
        }
        if (t + 1 < G1_KT) {            // stage next tile into alternate buffer
            const int nxt = cur ^ 1;
            if (tid < 128) {
                As[nxt][ac + 0][ar] = av.x; As[nxt][ac + 1][ar] = av.y;
                As[nxt][ac + 2][ar] = av.z; As[nxt][ac + 3][ar] = av.w;
            }
            *reinterpret_cast<float4*>(&Bs[nxt][br][bc]) = bv;
            __syncthreads();
        }
    }

#pragma unroll
    for (int i = 0; i < 4; i++) {
        int row = m0 + ty * 4 + i;
        if (row >= M) continue;
        float* cp = &C[(size_t)row * G1_N + n0];
#pragma unroll
        for (int g = 0; g < 2; g++) {   // two 4-col groups: tx*4 and 64+tx*4
            unsigned int l0, h0, l1, h1;
            asm("mov.b64 {%0, %1}, %2;" : "=r"(l0), "=r"(h0) : "l"(acc[i][2 * g + 0]));
            asm("mov.b64 {%0, %1}, %2;" : "=r"(l1), "=r"(h1) : "l"(acc[i][2 * g + 1]));
            *reinterpret_cast<float4*>(cp + g * 64 + tx * 4) =
                make_float4(__uint_as_float(l0), __uint_as_float(h0),
                            __uint_as_float(l1), __uint_as_float(h1));
        }
    }
}

// ---------------------------------------------------------------------------
// SGEMM fp32 (f32x2 FMA), single-buffered — layer 2 (relu fused on A load)
// ---------------------------------------------------------------------------
template <int BM, int BN, int BK, int TM, int TN, bool RELU_A>
__global__ __launch_bounds__((BM / TM) * (BN / TN))
void sgemm_k(const float* __restrict__ A, const float* __restrict__ B,
             float* __restrict__ C, int M, int N, int K)
{
    constexpr int NT  = (BM / TM) * (BN / TN);
    constexpr int TN2 = TN / 2;
    __shared__ __align__(16) float As[BK][BM];
    __shared__ __align__(16) float Bs[BK][BN];
    const int tid = threadIdx.x;
    const int tx  = tid % (BN / TN);
    const int ty  = tid / (BN / TN);
    const int m0  = blockIdx.y * BM;
    const int n0  = blockIdx.x * BN;

    unsigned long long acc[TM][TN2];
#pragma unroll
    for (int i = 0; i < TM; i++)
#pragma unroll
        for (int j = 0; j < TN2; j++) acc[i][j] = 0ull;

    for (int kk = 0; kk < K; kk += BK) {
        for (int i = tid; i < BM * BK / 4; i += NT) {
            int r = i / (BK / 4);
            int c = (i % (BK / 4)) * 4;
            float4 v = make_float4(0.f, 0.f, 0.f, 0.f);
            int row = m0 + r;
            if (row < M)
                v = *reinterpret_cast<const float4*>(&A[(size_t)row * K + kk + c]);
            if (RELU_A) {
                v.x = fmaxf(v.x, 0.f); v.y = fmaxf(v.y, 0.f);
                v.z = fmaxf(v.z, 0.f); v.w = fmaxf(v.w, 0.f);
            }
            As[c + 0][r] = v.x; As[c + 1][r] = v.y;
            As[c + 2][r] = v.z; As[c + 3][r] = v.w;
        }
        for (int i = tid; i < BK * BN / 4; i += NT) {
            int r = i / (BN / 4);
            int c = (i % (BN / 4)) * 4;
            *reinterpret_cast<float4*>(&Bs[r][c]) =
                *reinterpret_cast<const float4*>(&B[(size_t)(kk + r) * N + n0 + c]);
        }
        __syncthreads();
#pragma unroll
        for (int k = 0; k < BK; k++) {
            float a[TM];
#pragma unroll
            for (int i = 0; i < TM; i += 4) {
                float4 av = *reinterpret_cast<const float4*>(&As[k][ty * TM + i]);
                a[i] = av.x; a[i + 1] = av.y; a[i + 2] = av.z; a[i + 3] = av.w;
            }
            unsigned long long b2[TN2];
            const unsigned long long* bp =
                reinterpret_cast<const unsigned long long*>(&Bs[k][tx * TN]);
#pragma unroll
            for (int j = 0; j < TN2; j++) b2[j] = bp[j];
#pragma unroll
            for (int i = 0; i < TM; i++) {
                unsigned long long a2;
                unsigned int au = __float_as_uint(a[i]);
                asm("mov.b64 %0, {%1, %1};" : "=l"(a2) : "r"(au));
#pragma unroll
                for (int j = 0; j < TN2; j++) {
                    asm("fma.rn.f32x2 %0, %1, %2, %3;"
                        : "=l"(acc[i][j]) : "l"(a2), "l"(b2[j]), "l"(acc[i][j]));
                }
            }
        }
        __syncthreads();
    }
#pragma unroll
    for (int i = 0; i < TM; i++) {
        int row = m0 + ty * TM + i;
        if (row >= M) continue;
        float* cp = &C[(size_t)row * N + n0 + tx * TN];
#pragma unroll
        for (int j = 0; j < TN2; j++) {
            unsigned int lo, hi;
            asm("mov.b64 {%0, %1}, %2;" : "=r"(lo), "=r"(hi) : "l"(acc[i][j]));
            *reinterpret_cast<float2*>(cp + 2 * j) =
                make_float2(__uint_as_float(lo), __uint_as_float(hi));
        }
    }
}

// ---------------------------------------------------------------------------
// CSR aggregation (no atomics): out[d,:] = dinv[d]^2*h[d,:] + sum norm*h[src,:]
// ---------------------------------------------------------------------------
template <int D4, int LPN, int CPL>
__global__ void k_aggr(const float4* __restrict__ h4,
                       float4* __restrict__ o4, int n)
{
    int gt   = blockIdx.x * blockDim.x + threadIdx.x;
    int node = gt / LPN;
    int lane = threadIdx.x % LPN;
    if (node >= n) return;

    int beg = g_off[node];
    int end = beg + g_cnt[node];
    float w = g_dinv[node];
    w = w * w;

    float4 acc[CPL];
#pragma unroll
    for (int j = 0; j < CPL; j++) {
        float4 v = __ldg(&h4[(size_t)node * D4 + lane + j * LPN]);
        acc[j] = make_float4(v.x * w, v.y * w, v.z * w, v.w * w);
    }
    for (int e = beg; e < end; e++) {
        int   s  = __ldcs(&g_ssrc[e]);
        float nm = __ldcs(&g_snorm[e]);
#pragma unroll
        for (int j = 0; j < CPL; j++) {
            float4 v = __ldg(&h4[(size_t)s * D4 + lane + j * LPN]);
            acc[j].x += nm * v.x; acc[j].y += nm * v.y;
            acc[j].z += nm * v.z; acc[j].w += nm * v.w;
        }
    }
#pragma unroll
    for (int j = 0; j < CPL; j++)
        __stcs(&o4[(size_t)node * D4 + lane + j * LPN], acc[j]);
}

// ---------------------------------------------------------------------------
// Launch
// ---------------------------------------------------------------------------
extern "C" void kernel_launch(void* const* d_in, const int* in_sizes, int n_in,
                              void* d_out, int out_size)
{
    const float* x   = (const float*)d_in[0];   // [N, 512]
    const float* W1  = (const float*)d_in[1];   // [512, 256]
    const float* W2  = (const float*)d_in[2];   // [256, 64]
    const void*  ei  = d_in[3];                 // [2, E] int32 or int64
    float*       out = (float*)d_out;           // [N, 64]

    const int N = in_sizes[0] / INDIM;
    const int E = in_sizes[3] / 2;

    void *ph, *pa1, *ph2;
    cudaGetSymbolAddress(&ph,  g_h);
    cudaGetSymbolAddress(&pa1, g_a1);
    cudaGetSymbolAddress(&ph2, g_h2);
    float* h  = (float*)ph;
    float* a1 = (float*)pa1;
    float* h2 = (float*)ph2;

    const int TB = 256;
    const int NB = (N + 1023) / 1024;

    // edge dtype + degree count
    k_detect<<<1, 256>>>(ei, E, N);
    k_init  <<<(N + TB - 1) / TB, TB>>>(N);
    k_count <<<(E + TB - 1) / TB, TB>>>(ei, E);

    // layer-1 projection: double-buffered f32x2 GEMM, high occupancy
    {
        dim3 grid(HIDDIM / 128, (N + 63) / 64);
        gemm1_db<<<grid, 256>>>(x, W1, h, N);
    }

    // normalization + CSR build
    k_dinv <<<(N + TB - 1) / TB, TB>>>(N);
    k_scan1<<<NB, 1024>>>(N);
    k_scan2<<<1, 1024>>>(NB);
    k_scan3<<<(N + TB - 1) / TB, TB>>>(N);
    k_place<<<(E + TB - 1) / TB, TB>>>(ei, E);

    // layer-1 aggregation
    k_aggr<HIDDIM / 4, 32, 2><<<(N * 32 + TB - 1) / TB, TB>>>(
        (const float4*)h, (float4*)a1, N);

    // layer-2 projection (relu fused)
    {
        dim3 grid(OUTDIM / 64, (N + 127) / 128);
        sgemm_k<128, 64, 8, 8, 4, true><<<grid, 256>>>(a1, W2, h2, N, OUTDIM, HIDDIM);
    }

    // layer-2 aggregation
    k_aggr<OUTDIM / 4, 16, 1><<<(N * 16 + TB - 1) / TB, TB>>>(
        (const float4*)h2, (float4*)out, N);
}

// round 17
// speedup vs baseline: 1.0179x; 1.0179x over previous
#include <cuda_runtime.h>
#include <cstdint>

// Problem constants (shapes fixed by the reference).
#define NNODES 100000
#define INDIM  512
#define HIDDIM 256
#define OUTDIM 64
#define NEDGES 3200000

// ---------------------------------------------------------------------------
// Scratch (device globals — no runtime allocation allowed)
// ---------------------------------------------------------------------------
__device__ __align__(16) float g_dinv[NNODES];
__device__ __align__(16) int   g_cnt [NNODES];
__device__ __align__(16) int   g_off [NNODES];
__device__ __align__(16) int   g_pos [NNODES];
__device__ __align__(16) int   g_part[1024];
__device__ __align__(16) int   g_ssrc [NEDGES];
__device__ __align__(16) float g_snorm[NEDGES];
__device__ __align__(16) float g_h  [NNODES * HIDDIM];
__device__ __align__(16) float g_a1 [NNODES * HIDDIM];
__device__ __align__(16) float g_h2 [NNODES * OUTDIM];
__device__ int g_is64;

// ---------------------------------------------------------------------------
// Edge dtype detection (int64 vs int32 edge_index)
// ---------------------------------------------------------------------------
__global__ void k_detect(const void* __restrict__ ei, int E, int n) {
    int m = E < 1024 ? E : 1024;
    int ok = 1;
    const long long* p = (const long long*)ei;
    for (int i = threadIdx.x; i < m; i += blockDim.x) {
        long long v = p[i];
        if (v < 0 || v >= (long long)n) ok = 0;
    }
    int all = __syncthreads_and(ok);
    if (threadIdx.x == 0) g_is64 = all;
}
__device__ __forceinline__ int edge_at(const void* ei, long long idx) {
    if (g_is64) return (int)((const long long*)ei)[idx];
    return ((const int*)ei)[idx];
}

// ---------------------------------------------------------------------------
// Degree count + CSR build (bucketed by dst)
// ---------------------------------------------------------------------------
__global__ void k_init(int n) {
    int i = blockIdx.x * blockDim.x + threadIdx.x;
    if (i < n) g_cnt[i] = 0;
}
__global__ void k_count(const void* __restrict__ ei, int E) {
    int e = blockIdx.x * blockDim.x + threadIdx.x;
    if (e < E) atomicAdd(&g_cnt[edge_at(ei, (long long)E + e)], 1);
}
__global__ void k_dinv(int n) {
    int i = blockIdx.x * blockDim.x + threadIdx.x;
    if (i < n) g_dinv[i] = rsqrtf(1.0f + (float)g_cnt[i]);
}
__global__ void k_scan1(int n) {
    __shared__ int s[1024];
    int i = blockIdx.x * 1024 + threadIdx.x;
    int v = (i < n) ? g_cnt[i] : 0;
    s[threadIdx.x] = v;
    __syncthreads();
#pragma unroll
    for (int d = 1; d < 1024; d <<= 1) {
        int t = (threadIdx.x >= d) ? s[threadIdx.x - d] : 0;
        __syncthreads();
        s[threadIdx.x] += t;
        __syncthreads();
    }
    if (i < n) g_off[i] = s[threadIdx.x] - v;
    if (threadIdx.x == 1023) g_part[blockIdx.x] = s[1023];
}
__global__ void k_scan2(int nb) {
    __shared__ int s[1024];
    int v = (threadIdx.x < nb) ? g_part[threadIdx.x] : 0;
    s[threadIdx.x] = v;
    __syncthreads();
#pragma unroll
    for (int d = 1; d < 1024; d <<= 1) {
        int t = (threadIdx.x >= d) ? s[threadIdx.x - d] : 0;
        __syncthreads();
        s[threadIdx.x] += t;
        __syncthreads();
    }
    if (threadIdx.x < nb) g_part[threadIdx.x] = s[threadIdx.x] - v;
}
__global__ void k_scan3(int n) {
    int i = blockIdx.x * blockDim.x + threadIdx.x;
    if (i < n) {
        int o = g_off[i] + g_part[i >> 10];
        g_off[i] = o;
        g_pos[i] = o;
    }
}
__global__ void k_place(const void* __restrict__ ei, int E) {
    int e = blockIdx.x * blockDim.x + threadIdx.x;
    if (e < E) {
        int s = edge_at(ei, e);
        int d = edge_at(ei, (long long)E + e);
        int p = atomicAdd(&g_pos[d], 1);
        g_ssrc[p]  = s;
        g_snorm[p] = g_dinv[s] * g_dinv[d];
    }
}

// ---------------------------------------------------------------------------
// GEMM1: h[M,256] = x[M,512] @ W1[512,256]
// Round-15 thread tile (TM=8, TN=4+4 dense B) at HIGHER occupancy:
// BM=64, BN=128, 128 threads/CTA, 5 CTAs/SM (20 warps, 5/SMSP).
// B tiles stream gmem->smem via cp.async (no registers, no STS);
// A keeps the register+STS transpose path. Double-buffered, 1 sync/tile.
// ---------------------------------------------------------------------------
#define G1_K 512
#define G1_N 256
#define G1_KT (G1_K / 8)   // 64 K-tiles

__device__ __forceinline__ uint32_t smem_u32(const void* p) {
    uint32_t a;
    asm("{ .reg .u64 t; cvta.to.shared.u64 t, %1; cvt.u32.u64 %0, t; }"
        : "=r"(a) : "l"(p));
    return a;
}
#define CP_ASYNC16(sa, gp) \
    asm volatile("cp.async.cg.shared.global [%0], [%1], 16;" \
                 :: "r"(sa), "l"(gp) : "memory")
#define CP_COMMIT()  asm volatile("cp.async.commit_group;" ::: "memory")
#define CP_WAIT0()   asm volatile("cp.async.wait_group 0;" ::: "memory")

__global__ __launch_bounds__(128, 5)
void gemm1_db(const float* __restrict__ A, const float* __restrict__ B,
              float* __restrict__ C, int M)
{
    __shared__ __align__(16) float As[2][8][64];    // 2 KB x2
    __shared__ __align__(16) float Bs[2][8][128];   // 4 KB x2

    const int tid = threadIdx.x;
    const int tx  = tid & 15;          // 16 col-groups; cols tx*4 and 64+tx*4
    const int ty  = tid >> 4;          // 8 row-groups * 8 = 64 M rows
    const int m0  = blockIdx.y * 64;
    const int n0  = blockIdx.x * 128;

    const int ar = tid >> 1, ac = (tid & 1) * 4;     // A: 64x8 = 128 float4, 1/thread
    const int br0 = tid >> 5,        bc0 = (tid & 31) * 4;   // B chunk 0
    const int br1 = (tid + 128) >> 5, bc1 = (tid & 31) * 4;  // B chunk 1
    const float4 fz = make_float4(0.f, 0.f, 0.f, 0.f);

    const uint32_t bs_base = smem_u32(&Bs[0][0][0]);
    const uint32_t b_sa0 = bs_base + (uint32_t)(br0 * 128 + bc0) * 4u;
    const uint32_t b_sa1 = bs_base + (uint32_t)(br1 * 128 + bc1) * 4u;

    // prologue: tile 0
    float4 av = (m0 + ar < M)
        ? *reinterpret_cast<const float4*>(&A[(size_t)(m0 + ar) * G1_K + ac]) : fz;
    As[0][ac + 0][ar] = av.x; As[0][ac + 1][ar] = av.y;
    As[0][ac + 2][ar] = av.z; As[0][ac + 3][ar] = av.w;
    CP_ASYNC16(b_sa0, &B[(size_t)br0 * G1_N + n0 + bc0]);
    CP_ASYNC16(b_sa1, &B[(size_t)br1 * G1_N + n0 + bc1]);
    CP_COMMIT();
    CP_WAIT0();
    __syncthreads();

    unsigned long long acc[8][4];      // j=0,1: cols tx*4+{0,2}; j=2,3: 64+tx*4+{0,2}
#pragma unroll
    for (int i = 0; i < 8; i++)
#pragma unroll
        for (int j = 0; j < 4; j++) acc[i][j] = 0ull;

    const uint32_t bs_stride = 8u * 128u * 4u;       // one stage of Bs

    for (int t = 0; t < G1_KT; t++) {
        const int cur = t & 1;
        const int nxt = cur ^ 1;
        if (t + 1 < G1_KT) {            // start next tile: A->reg, B->smem async
            const int kk = (t + 1) * 8;
            av = (m0 + ar < M)
                ? *reinterpret_cast<const float4*>(&A[(size_t)(m0 + ar) * G1_K + kk + ac]) : fz;
            CP_ASYNC16(b_sa0 + nxt * bs_stride, &B[(size_t)(kk + br0) * G1_N + n0 + bc0]);
            CP_ASYNC16(b_sa1 + nxt * bs_stride, &B[(size_t)(kk + br1) * G1_N + n0 + bc1]);
            CP_COMMIT();
        }
#pragma unroll
        for (int k = 0; k < 8; k++) {
            float4 av0 = *reinterpret_cast<const float4*>(&As[cur][k][ty * 8 + 0]);
            float4 av1 = *reinterpret_cast<const float4*>(&As[cur][k][ty * 8 + 4]);
            float a[8] = {av0.x, av0.y, av0.z, av0.w, av1.x, av1.y, av1.z, av1.w};
            ulonglong2 bg0 = *reinterpret_cast<const ulonglong2*>(&Bs[cur][k][tx * 4]);
            ulonglong2 bg1 = *reinterpret_cast<const ulonglong2*>(&Bs[cur][k][64 + tx * 4]);
            unsigned long long b2[4] = {bg0.x, bg0.y, bg1.x, bg1.y};
#pragma unroll
            for (int i = 0; i < 8; i++) {
                unsigned long long a2;
                unsigned int au = __float_as_uint(a[i]);
                asm("mov.b64 %0, {%1, %1};" : "=l"(a2) : "r"(au));
#pragma unroll
                for (int j = 0; j < 4; j++)
                    asm("fma.rn.f32x2 %0, %1, %2, %3;"
                        : "=l"(acc[i][j]) : "l"(a2), "l"(b2[j]), "l"(acc[i][j]));
            }
        }
        if (t + 1 < G1_KT) {            // stage A, drain B copy, flip
            As[nxt][ac + 0][ar] = av.x; As[nxt][ac + 1][ar] = av.y;
            As[nxt][ac + 2][ar] = av.z; As[nxt][ac + 3][ar] = av.w;
            CP_WAIT0();
            __syncthreads();
        }
    }

#pragma unroll
    for (int i = 0; i < 8; i++) {
        int row = m0 + ty * 8 + i;
        if (row >= M) continue;
        float* cp = &C[(size_t)row * G1_N + n0];
#pragma unroll
        for (int g = 0; g < 2; g++) {   // two 4-col groups: tx*4 and 64+tx*4
            unsigned int l0, h0, l1, h1;
            asm("mov.b64 {%0, %1}, %2;" : "=r"(l0), "=r"(h0) : "l"(acc[i][2 * g + 0]));
            asm("mov.b64 {%0, %1}, %2;" : "=r"(l1), "=r"(h1) : "l"(acc[i][2 * g + 1]));
            *reinterpret_cast<float4*>(cp + g * 64 + tx * 4) =
                make_float4(__uint_as_float(l0), __uint_as_float(h0),
                            __uint_as_float(l1), __uint_as_float(h1));
        }
    }
}

// ---------------------------------------------------------------------------
// SGEMM fp32 (f32x2 FMA), single-buffered — layer 2 (relu fused on A load)
// ---------------------------------------------------------------------------
template <int BM, int BN, int BK, int TM, int TN, bool RELU_A>
__global__ __launch_bounds__((BM / TM) * (BN / TN))
void sgemm_k(const float* __restrict__ A, const float* __restrict__ B,
             float* __restrict__ C, int M, int N, int K)
{
    constexpr int NT  = (BM / TM) * (BN / TN);
    constexpr int TN2 = TN / 2;
    __shared__ __align__(16) float As[BK][BM];
    __shared__ __align__(16) float Bs[BK][BN];
    const int tid = threadIdx.x;
    const int tx  = tid % (BN / TN);
    const int ty  = tid / (BN / TN);
    const int m0  = blockIdx.y * BM;
    const int n0  = blockIdx.x * BN;

    unsigned long long acc[TM][TN2];
#pragma unroll
    for (int i = 0; i < TM; i++)
#pragma unroll
        for (int j = 0; j < TN2; j++) acc[i][j] = 0ull;

    for (int kk = 0; kk < K; kk += BK) {
        for (int i = tid; i < BM * BK / 4; i += NT) {
            int r = i / (BK / 4);
            int c = (i % (BK / 4)) * 4;
            float4 v = make_float4(0.f, 0.f, 0.f, 0.f);
            int row = m0 + r;
            if (row < M)
                v = *reinterpret_cast<const float4*>(&A[(size_t)row * K + kk + c]);
            if (RELU_A) {
                v.x = fmaxf(v.x, 0.f); v.y = fmaxf(v.y, 0.f);
                v.z = fmaxf(v.z, 0.f); v.w = fmaxf(v.w, 0.f);
            }
            As[c + 0][r] = v.x; As[c + 1][r] = v.y;
            As[c + 2][r] = v.z; As[c + 3][r] = v.w;
        }
        for (int i = tid; i < BK * BN / 4; i += NT) {
            int r = i / (BN / 4);
            int c = (i % (BN / 4)) * 4;
            *reinterpret_cast<float4*>(&Bs[r][c]) =
                *reinterpret_cast<const float4*>(&B[(size_t)(kk + r) * N + n0 + c]);
        }
        __syncthreads();
#pragma unroll
        for (int k = 0; k < BK; k++) {
            float a[TM];
#pragma unroll
            for (int i = 0; i < TM; i += 4) {
                float4 av = *reinterpret_cast<const float4*>(&As[k][ty * TM + i]);
                a[i] = av.x; a[i + 1] = av.y; a[i + 2] = av.z; a[i + 3] = av.w;
            }
            unsigned long long b2[TN2];
            const unsigned long long* bp =
                reinterpret_cast<const unsigned long long*>(&Bs[k][tx * TN]);
#pragma unroll
            for (int j = 0; j < TN2; j++) b2[j] = bp[j];
#pragma unroll
            for (int i = 0; i < TM; i++) {
                unsigned long long a2;
                unsigned int au = __float_as_uint(a[i]);
                asm("mov.b64 %0, {%1, %1};" : "=l"(a2) : "r"(au));
#pragma unroll
                for (int j = 0; j < TN2; j++) {
                    asm("fma.rn.f32x2 %0, %1, %2, %3;"
                        : "=l"(acc[i][j]) : "l"(a2), "l"(b2[j]), "l"(acc[i][j]));
                }
            }
        }
        __syncthreads();
    }
#pragma unroll
    for (int i = 0; i < TM; i++) {
        int row = m0 + ty * TM + i;
        if (row >= M) continue;
        float* cp = &C[(size_t)row * N + n0 + tx * TN];
#pragma unroll
        for (int j = 0; j < TN2; j++) {
            unsigned int lo, hi;
            asm("mov.b64 {%0, %1}, %2;" : "=r"(lo), "=r"(hi) : "l"(acc[i][j]));
            *reinterpret_cast<float2*>(cp + 2 * j) =
                make_float2(__uint_as_float(lo), __uint_as_float(hi));
        }
    }
}

// ---------------------------------------------------------------------------
// CSR aggregation (no atomics): out[d,:] = dinv[d]^2*h[d,:] + sum norm*h[src,:]
// ---------------------------------------------------------------------------
template <int D4, int LPN, int CPL>
__global__ void k_aggr(const float4* __restrict__ h4,
                       float4* __restrict__ o4, int n)
{
    int gt   = blockIdx.x * blockDim.x + threadIdx.x;
    int node = gt / LPN;
    int lane = threadIdx.x % LPN;
    if (node >= n) return;

    int beg = g_off[node];
    int end = beg + g_cnt[node];
    float w = g_dinv[node];
    w = w * w;

    float4 acc[CPL];
#pragma unroll
    for (int j = 0; j < CPL; j++) {
        float4 v = __ldg(&h4[(size_t)node * D4 + lane + j * LPN]);
        acc[j] = make_float4(v.x * w, v.y * w, v.z * w, v.w * w);
    }
    for (int e = beg; e < end; e++) {
        int   s  = __ldcs(&g_ssrc[e]);
        float nm = __ldcs(&g_snorm[e]);
#pragma unroll
        for (int j = 0; j < CPL; j++) {
            float4 v = __ldg(&h4[(size_t)s * D4 + lane + j * LPN]);
            acc[j].x += nm * v.x; acc[j].y += nm * v.y;
            acc[j].z += nm * v.z; acc[j].w += nm * v.w;
        }
    }
#pragma unroll
    for (int j = 0; j < CPL; j++)
        __stcs(&o4[(size_t)node * D4 + lane + j * LPN], acc[j]);
}

// ---------------------------------------------------------------------------
// Launch
// ---------------------------------------------------------------------------
extern "C" void kernel_launch(void* const* d_in, const int* in_sizes, int n_in,
                              void* d_out, int out_size)
{
    const float* x   = (const float*)d_in[0];   // [N, 512]
    const float* W1  = (const float*)d_in[1];   // [512, 256]
    const float* W2  = (const float*)d_in[2];   // [256, 64]
    const void*  ei  = d_in[3];                 // [2, E] int32 or int64
    float*       out = (float*)d_out;           // [N, 64]

    const int N = in_sizes[0] / INDIM;
    const int E = in_sizes[3] / 2;

    void *ph, *pa1, *ph2;
    cudaGetSymbolAddress(&ph,  g_h);
    cudaGetSymbolAddress(&pa1, g_a1);
    cudaGetSymbolAddress(&ph2, g_h2);
    float* h  = (float*)ph;
    float* a1 = (float*)pa1;
    float* h2 = (float*)ph2;

    const int TB = 256;
    const int NB = (N + 1023) / 1024;

    // edge dtype + degree count
    k_detect<<<1, 256>>>(ei, E, N);
    k_init  <<<(N + TB - 1) / TB, TB>>>(N);
    k_count <<<(E + TB - 1) / TB, TB>>>(ei, E);

    // layer-1 projection: double-buffered f32x2 GEMM, 5 CTAs/SM + cp.async B
    {
        dim3 grid(HIDDIM / 128, (N + 63) / 64);
        gemm1_db<<<grid, 128>>>(x, W1, h, N);
    }

    // normalization + CSR build
    k_dinv <<<(N + TB - 1) / TB, TB>>>(N);
    k_scan1<<<NB, 1024>>>(N);
    k_scan2<<<1, 1024>>>(NB);
    k_scan3<<<(N + TB - 1) / TB, TB>>>(N);
    k_place<<<(E + TB - 1) / TB, TB>>>(ei, E);

    // layer-1 aggregation
    k_aggr<HIDDIM / 4, 32, 2><<<(N * 32 + TB - 1) / TB, TB>>>(
        (const float4*)h, (float4*)a1, N);

    // layer-2 projection (relu fused)
    {
        dim3 grid(OUTDIM / 64, (N + 127) / 128);
        sgemm_k<128, 64, 8, 8, 4, true><<<grid, 256>>>(a1, W2, h2, N, OUTDIM, HIDDIM);
    }

    // layer-2 aggregation
    k_aggr<OUTDIM / 4, 16, 1><<<(N * 16 + TB - 1) / TB, TB>>>(
        (const float4*)h2, (float4*)out, N);
}